// round 1
// baseline (speedup 1.0000x reference)
#include <cuda_runtime.h>
#include <cuda_bf16.h>

#define B_SZ 32
#define F_SZ 257
#define T_SZ 3000
#define T4_SZ (T_SZ / 4)          // 750 float4 per row
#define NCHUNK 4
#define FCHUNK 65                 // 65,65,65,62 covers 257
#define MOMENTUM 0.99f
#define ONE_MINUS_M (1.0f - 0.99f)
#define EPS 1e-8f

// Scratch (static device globals; no allocation in kernel_launch)
__device__ __align__(16) float g_partial[NCHUNK * B_SZ * T_SZ];  // partial col sums
__device__ __align__(16) float g_inv[B_SZ * T_SZ];               // 1/(mean+bias+eps)

// ---------------------------------------------------------------------------
// k1: partial column sums over F-chunks, float4 vectorized over T.
// grid: (ceil(T4/128), NCHUNK, B), block: 128
// ---------------------------------------------------------------------------
__global__ void ema_k1_colsum(const float* __restrict__ mag) {
    int t4 = blockIdx.x * blockDim.x + threadIdx.x;
    if (t4 >= T4_SZ) return;
    int ch = blockIdx.y;
    int b  = blockIdx.z;

    int f0 = ch * FCHUNK;
    int f1 = f0 + FCHUNK;
    if (f1 > F_SZ) f1 = F_SZ;

    const float4* base = reinterpret_cast<const float4*>(mag + (size_t)b * F_SZ * T_SZ) + t4;

    float4 s = make_float4(0.f, 0.f, 0.f, 0.f);
    int f = f0;
    #pragma unroll 1
    for (; f + 4 <= f1; f += 4) {
        float4 v0 = base[(size_t)(f + 0) * T4_SZ];
        float4 v1 = base[(size_t)(f + 1) * T4_SZ];
        float4 v2 = base[(size_t)(f + 2) * T4_SZ];
        float4 v3 = base[(size_t)(f + 3) * T4_SZ];
        s.x += v0.x + v1.x + v2.x + v3.x;
        s.y += v0.y + v1.y + v2.y + v3.y;
        s.z += v0.z + v1.z + v2.z + v3.z;
        s.w += v0.w + v1.w + v2.w + v3.w;
    }
    for (; f < f1; f++) {
        float4 v = base[(size_t)f * T4_SZ];
        s.x += v.x; s.y += v.y; s.z += v.z; s.w += v.w;
    }
    reinterpret_cast<float4*>(g_partial)[((size_t)ch * B_SZ + b) * T4_SZ + t4] = s;
}

// ---------------------------------------------------------------------------
// k2: per-batch EMA scan (linear recurrence m_t = a*m_{t-1} + (1-a)*x_t)
// via pair composition block scan. grid: B blocks of 128 threads.
// Each thread owns a 24-element contiguous segment (128*24 = 3072 >= 3000).
// Writes g_inv and the mag_mean section of d_out.
// ---------------------------------------------------------------------------
#define SEG 24
__global__ void ema_k2_scan(const float* __restrict__ bias,
                            const float* __restrict__ running_mean,
                            float* __restrict__ out_mean /* d_out + B*F*T */) {
    int b   = blockIdx.x;
    int tid = threadIdx.x;   // 0..127
    int t0  = tid * SEG;

    float x[SEG];
    float A = 1.0f, Bacc = 0.0f;

    const float* p0 = g_partial + ((size_t)0 * B_SZ + b) * T_SZ;
    const float* p1 = g_partial + ((size_t)1 * B_SZ + b) * T_SZ;
    const float* p2 = g_partial + ((size_t)2 * B_SZ + b) * T_SZ;
    const float* p3 = g_partial + ((size_t)3 * B_SZ + b) * T_SZ;

    #pragma unroll
    for (int j = 0; j < SEG; j++) {
        int t = t0 + j;
        if (t < T_SZ) {
            float s  = p0[t] + p1[t] + p2[t] + p3[t];
            float fm = s * (1.0f / (float)F_SZ);
            x[j] = fm;
            A    = MOMENTUM * A;
            Bacc = MOMENTUM * Bacc + ONE_MINUS_M * fm;
        }
    }

    // Hillis-Steele inclusive scan over (A, Bacc) pairs; composition:
    // (a2,b2) after (a1,b1) -> (a2*a1, a2*b1 + b2)
    __shared__ float sA[128], sB[128];
    sA[tid] = A; sB[tid] = Bacc;
    __syncthreads();
    for (int off = 1; off < 128; off <<= 1) {
        float a2 = sA[tid], b2 = sB[tid];
        float a1 = 1.0f, b1 = 0.0f;
        if (tid >= off) { a1 = sA[tid - off]; b1 = sB[tid - off]; }
        __syncthreads();
        sA[tid] = a2 * a1;
        sB[tid] = a2 * b1 + b2;
        __syncthreads();
    }

    // Exclusive prefix for this thread = inclusive of tid-1
    float Ap = 1.0f, Bp = 0.0f;
    if (tid > 0) { Ap = sA[tid - 1]; Bp = sB[tid - 1]; }

    float m  = Ap * running_mean[0] + Bp;   // EMA state entering this segment
    float bi = bias[0];

    float*       invp  = g_inv + (size_t)b * T_SZ;
    float*       meanp = out_mean + (size_t)b * T_SZ;

    #pragma unroll
    for (int j = 0; j < SEG; j++) {
        int t = t0 + j;
        if (t < T_SZ) {
            m = MOMENTUM * m + ONE_MINUS_M * x[j];
            float mwb = m + bi;
            invp[t]  = 1.0f / (mwb + EPS);
            meanp[t] = mwb;
        }
    }
}

// ---------------------------------------------------------------------------
// k3: mag_norm = mag * inv[b,t], float4 vectorized.
// grid: (ceil(T4/256), F, B), block: 256
// ---------------------------------------------------------------------------
__global__ void ema_k3_norm(const float* __restrict__ mag,
                            float* __restrict__ out_norm) {
    int t4 = blockIdx.x * blockDim.x + threadIdx.x;
    if (t4 >= T4_SZ) return;
    int f = blockIdx.y;
    int b = blockIdx.z;

    size_t row = ((size_t)b * F_SZ + f) * T4_SZ + t4;
    float4 v  = reinterpret_cast<const float4*>(mag)[row];
    float4 iv = reinterpret_cast<const float4*>(g_inv)[(size_t)b * T4_SZ + t4];
    v.x *= iv.x; v.y *= iv.y; v.z *= iv.z; v.w *= iv.w;
    reinterpret_cast<float4*>(out_norm)[row] = v;
}

// ---------------------------------------------------------------------------
extern "C" void kernel_launch(void* const* d_in, const int* in_sizes, int n_in,
                              void* d_out, int out_size) {
    const float* mag          = (const float*)d_in[0];
    const float* bias         = (const float*)d_in[1];
    const float* running_mean = (const float*)d_in[2];
    float* out = (float*)d_out;

    float* out_norm = out;                                // [B, F, T]
    float* out_mean = out + (size_t)B_SZ * F_SZ * T_SZ;   // [B, 1, T]

    // k1: partial column sums
    {
        dim3 grid((T4_SZ + 127) / 128, NCHUNK, B_SZ);
        ema_k1_colsum<<<grid, 128>>>(mag);
    }
    // k2: scan + reciprocal + mag_mean output
    {
        ema_k2_scan<<<B_SZ, 128>>>(bias, running_mean, out_mean);
    }
    // k3: normalize
    {
        dim3 grid((T4_SZ + 255) / 256, F_SZ, B_SZ);
        ema_k3_norm<<<grid, 256>>>(mag, out_norm);
    }
}

// round 2
// speedup vs baseline: 1.2737x; 1.2737x over previous
#include <cuda_runtime.h>
#include <cuda_bf16.h>

#define B_SZ 32
#define F_SZ 257
#define T_SZ 3000
#define T4_SZ (T_SZ / 4)          // 750 float4 per row
#define NCHUNK 8
#define FCHUNK 33                 // 7*33 + 26 = 257
#define MOMENTUM 0.99f
#define ONE_MINUS_M (1.0f - 0.99f)
#define EPS 1e-8f

// Scratch (static device globals; no allocation in kernel_launch)
__device__ __align__(16) float g_partial[NCHUNK * B_SZ * T_SZ];  // partial col sums
__device__ __align__(16) float g_inv[B_SZ * T_SZ];               // 1/(mean+bias+eps)

// ---------------------------------------------------------------------------
// k1: partial column sums over F-chunks, float4 vectorized over T.
// grid: (ceil(T4/128), NCHUNK, B), block: 128.  8-deep load batching for MLP.
// ---------------------------------------------------------------------------
__global__ void ema_k1_colsum(const float* __restrict__ mag) {
    int t4 = blockIdx.x * blockDim.x + threadIdx.x;
    if (t4 >= T4_SZ) return;
    int ch = blockIdx.y;
    int b  = blockIdx.z;

    int f0 = ch * FCHUNK;
    int f1 = f0 + FCHUNK;
    if (f1 > F_SZ) f1 = F_SZ;

    const float4* base = reinterpret_cast<const float4*>(mag + (size_t)b * F_SZ * T_SZ) + t4;

    float4 s = make_float4(0.f, 0.f, 0.f, 0.f);
    int f = f0;
    #pragma unroll 1
    for (; f + 8 <= f1; f += 8) {
        float4 v0 = base[(size_t)(f + 0) * T4_SZ];
        float4 v1 = base[(size_t)(f + 1) * T4_SZ];
        float4 v2 = base[(size_t)(f + 2) * T4_SZ];
        float4 v3 = base[(size_t)(f + 3) * T4_SZ];
        float4 v4 = base[(size_t)(f + 4) * T4_SZ];
        float4 v5 = base[(size_t)(f + 5) * T4_SZ];
        float4 v6 = base[(size_t)(f + 6) * T4_SZ];
        float4 v7 = base[(size_t)(f + 7) * T4_SZ];
        s.x += ((v0.x + v1.x) + (v2.x + v3.x)) + ((v4.x + v5.x) + (v6.x + v7.x));
        s.y += ((v0.y + v1.y) + (v2.y + v3.y)) + ((v4.y + v5.y) + (v6.y + v7.y));
        s.z += ((v0.z + v1.z) + (v2.z + v3.z)) + ((v4.z + v5.z) + (v6.z + v7.z));
        s.w += ((v0.w + v1.w) + (v2.w + v3.w)) + ((v4.w + v5.w) + (v6.w + v7.w));
    }
    for (; f < f1; f++) {
        float4 v = base[(size_t)f * T4_SZ];
        s.x += v.x; s.y += v.y; s.z += v.z; s.w += v.w;
    }
    reinterpret_cast<float4*>(g_partial)[((size_t)ch * B_SZ + b) * T4_SZ + t4] = s;
}

// ---------------------------------------------------------------------------
// k2: per-batch EMA scan via pair-composition block scan.
// grid: B blocks of 256 threads; each thread owns SEG=12 contiguous t
// (256*12 = 3072 >= 3000). Writes g_inv and the mag_mean output.
// ---------------------------------------------------------------------------
#define SCAN_THREADS 256
#define SEG 12
__global__ void ema_k2_scan(const float* __restrict__ bias,
                            const float* __restrict__ running_mean,
                            float* __restrict__ out_mean /* d_out + B*F*T */) {
    int b   = blockIdx.x;
    int tid = threadIdx.x;   // 0..255
    int t0  = tid * SEG;

    float x[SEG];
    float A = 1.0f, Bacc = 0.0f;

    #pragma unroll
    for (int j = 0; j < SEG; j++) {
        int t = t0 + j;
        if (t < T_SZ) {
            float s = 0.0f;
            #pragma unroll
            for (int c = 0; c < NCHUNK; c++)
                s += g_partial[((size_t)c * B_SZ + b) * T_SZ + t];
            float fm = s * (1.0f / (float)F_SZ);
            x[j] = fm;
            A    = MOMENTUM * A;
            Bacc = MOMENTUM * Bacc + ONE_MINUS_M * fm;
        }
    }

    // Hillis-Steele inclusive scan over (A, Bacc); composition:
    // (a2,b2) after (a1,b1) -> (a2*a1, a2*b1 + b2)
    __shared__ float sA[SCAN_THREADS], sB[SCAN_THREADS];
    sA[tid] = A; sB[tid] = Bacc;
    __syncthreads();
    #pragma unroll
    for (int off = 1; off < SCAN_THREADS; off <<= 1) {
        float a2 = sA[tid], b2 = sB[tid];
        float a1 = 1.0f, b1 = 0.0f;
        if (tid >= off) { a1 = sA[tid - off]; b1 = sB[tid - off]; }
        __syncthreads();
        sA[tid] = a2 * a1;
        sB[tid] = a2 * b1 + b2;
        __syncthreads();
    }

    // Exclusive prefix for this thread = inclusive of tid-1
    float Ap = 1.0f, Bp = 0.0f;
    if (tid > 0) { Ap = sA[tid - 1]; Bp = sB[tid - 1]; }

    float m  = Ap * running_mean[0] + Bp;   // EMA state entering this segment
    float bi = bias[0];

    float* invp  = g_inv + (size_t)b * T_SZ;
    float* meanp = out_mean + (size_t)b * T_SZ;

    #pragma unroll
    for (int j = 0; j < SEG; j++) {
        int t = t0 + j;
        if (t < T_SZ) {
            m = MOMENTUM * m + ONE_MINUS_M * x[j];
            float mwb = m + bi;
            invp[t]  = 1.0f / (mwb + EPS);
            meanp[t] = mwb;
        }
    }
}

// ---------------------------------------------------------------------------
// k3: mag_norm = mag * inv[b,t], float4 vectorized, streaming stores so the
// output writes don't evict mag from L2 (mag should be L2-resident after k1).
// grid: (ceil(T4/256), F, B), block: 256
// ---------------------------------------------------------------------------
__global__ void ema_k3_norm(const float* __restrict__ mag,
                            float* __restrict__ out_norm) {
    int t4 = blockIdx.x * blockDim.x + threadIdx.x;
    if (t4 >= T4_SZ) return;
    int f = blockIdx.y;
    int b = blockIdx.z;

    size_t row = ((size_t)b * F_SZ + f) * T4_SZ + t4;
    float4 v  = reinterpret_cast<const float4*>(mag)[row];
    float4 iv = __ldca(reinterpret_cast<const float4*>(g_inv) + (size_t)b * T4_SZ + t4);
    v.x *= iv.x; v.y *= iv.y; v.z *= iv.z; v.w *= iv.w;
    __stcs(reinterpret_cast<float4*>(out_norm) + row, v);
}

// ---------------------------------------------------------------------------
extern "C" void kernel_launch(void* const* d_in, const int* in_sizes, int n_in,
                              void* d_out, int out_size) {
    const float* mag          = (const float*)d_in[0];
    const float* bias         = (const float*)d_in[1];
    const float* running_mean = (const float*)d_in[2];
    float* out = (float*)d_out;

    float* out_norm = out;                                // [B, F, T]
    float* out_mean = out + (size_t)B_SZ * F_SZ * T_SZ;   // [B, 1, T]

    // k1: partial column sums
    {
        dim3 grid((T4_SZ + 127) / 128, NCHUNK, B_SZ);
        ema_k1_colsum<<<grid, 128>>>(mag);
    }
    // k2: scan + reciprocal + mag_mean output
    {
        ema_k2_scan<<<B_SZ, SCAN_THREADS>>>(bias, running_mean, out_mean);
    }
    // k3: normalize
    {
        dim3 grid((T4_SZ + 255) / 256, F_SZ, B_SZ);
        ema_k3_norm<<<grid, 256>>>(mag, out_norm);
    }
}